// round 13
// baseline (speedup 1.0000x reference)
#include <cuda_runtime.h>
#include <stdint.h>

// ============================================================================
// HopfieldNet — bit-exact reference model (locked Round 7):
//   PRNG:    JAX partitionable threefry: bits[t] = o0 ^ o1 of tf2x32(key,(0,t))
//   GEMM:    exact fp32, per-element single ascending-k FMA chain (FFMA2 packed,
//            per-lane rn — bit-identical to scalar)
//   sigmoid: p = 1/(1+exp(-z)), z = (2*h)*(1/T), libdevice expf, div.rn
// Round 13: fully-async double buffer — BOTH tiles via cp.async (A stored
// row-major, read as scalar broadcasts; no reg staging, no smem transpose),
// BKT=32 (half the barriers), one wait+sync per tile. 68KB dynamic smem.
// ============================================================================

#define NB   65536
#define ND   1024
#define NTOT (NB * ND)

#define BM 128
#define BN 128
#define BKT 32
#define NKT (ND / BKT)
#define TM 8
#define TN 8
#define ASTRIDE 36              // padded row stride (floats); 144B, 16B-aligned

#define A_TILE_FLOATS (BM * ASTRIDE)        // 4608
#define B_TILE_FLOATS (BKT * BN)            // 4096
#define SMEM_FLOATS   (2 * A_TILE_FLOATS + 2 * B_TILE_FLOATS)
#define SMEM_BYTES    (SMEM_FLOATS * 4)     // 69632 B

__device__ float g_W [ND * ND];
__device__ float g_xA[NTOT];
__device__ float g_xB[NTOT];

// ---------------------------------------------------------------- threefry
__device__ __forceinline__ void tf2x32(uint32_t k0, uint32_t k1,
                                       uint32_t c0, uint32_t c1,
                                       uint32_t &o0, uint32_t &o1) {
    uint32_t ks2 = k0 ^ k1 ^ 0x1BD11BDAu;
    uint32_t x0 = c0 + k0;
    uint32_t x1 = c1 + k1;
#define TF_R(r) { x0 += x1; x1 = __funnelshift_l(x1, x1, (r)); x1 ^= x0; }
    TF_R(13) TF_R(15) TF_R(26) TF_R(6)   x0 += k1;  x1 += ks2 + 1u;
    TF_R(17) TF_R(29) TF_R(16) TF_R(24)  x0 += ks2; x1 += k0  + 2u;
    TF_R(13) TF_R(15) TF_R(26) TF_R(6)   x0 += k0;  x1 += k1  + 3u;
    TF_R(17) TF_R(29) TF_R(16) TF_R(24)  x0 += k1;  x1 += ks2 + 4u;
    TF_R(13) TF_R(15) TF_R(26) TF_R(6)   x0 += ks2; x1 += k0  + 5u;
#undef TF_R
    o0 = x0; o1 = x1;
}

__device__ __forceinline__ float jax_uniform(uint32_t k0, uint32_t k1, uint32_t t) {
    uint32_t o0, o1;
    tf2x32(k0, k1, 0u, t, o0, o1);
    uint32_t bits = o0 ^ o1;
    return __uint_as_float((bits >> 9) | 0x3f800000u) - 1.0f;
}

__device__ __forceinline__ float act(float h, float rT,
                                     uint32_t k0, uint32_t k1, uint32_t t) {
    float u = jax_uniform(k0, k1, t);
    float z = __fmul_rn(__fmul_rn(2.0f, h), rT);
    float e = expf(-z);
    float p = __fdiv_rn(1.0f, __fadd_rn(1.0f, e));
    return (u < p) ? 1.0f : -1.0f;
}

// ---------------------------------------------------------------- f32x2 ops
__device__ __forceinline__ uint64_t dup_f32x2(float a) {
    uint64_t r;
    asm("mov.b64 %0, {%1, %1};" : "=l"(r) : "f"(a));
    return r;
}
__device__ __forceinline__ void ffma2(uint64_t &acc, uint64_t a2, uint64_t b2) {
    asm("fma.rn.f32x2 %0, %1, %2, %0;" : "+l"(acc) : "l"(a2), "l"(b2));
}
__device__ __forceinline__ void unpack_f32x2(uint64_t v, float &lo, float &hi) {
    asm("mov.b64 {%0, %1}, %2;" : "=f"(lo), "=f"(hi) : "l"(v));
}

// ---------------------------------------------------------------- cp.async
__device__ __forceinline__ uint32_t smem_u32(const void* p) {
    return (uint32_t)__cvta_generic_to_shared(p);
}
__device__ __forceinline__ void cp_async16(uint32_t dst, const void* src) {
    asm volatile("cp.async.cg.shared.global [%0], [%1], 16;"
                 :: "r"(dst), "l"(src));
}
__device__ __forceinline__ void cp_async_commit() {
    asm volatile("cp.async.commit_group;");
}
__device__ __forceinline__ void cp_async_wait0() {
    asm volatile("cp.async.wait_group 0;");
}

// ---------------------------------------------------------------- W = Wu+Wu^T
__global__ void prep_W(const float* __restrict__ Wu) {
    int idx = blockIdx.x * blockDim.x + threadIdx.x;
    int k = idx >> 10;
    int j = idx & 1023;
    g_W[idx] = __fadd_rn(Wu[idx], Wu[j * ND + k]);
}

// ---------------------------------------------------------------- fused step
// 256 threads, 8x8 outputs/thread, FFMA2 inner product.
// A tile row-major [m][k] (scalar broadcast reads), B tile [k][n] (vector
// reads). Both tiles double-buffered via cp.async; one sync per 32-kk tile.
__global__ void __launch_bounds__(256)
hop_step(const float* __restrict__ X, float* __restrict__ O,
         uint32_t k0, uint32_t k1, float rT) {
    extern __shared__ float smem[];
    float* Asm = smem;                         // [2][BM][ASTRIDE]
    float* Bsm = smem + 2 * A_TILE_FLOATS;     // [2][BKT][BN]

    const int tid = threadIdx.x;
    const int tx  = tid & 15;
    const int ty  = tid >> 4;

    const int row0 = blockIdx.y * BM;
    const int col0 = blockIdx.x * BN;

    // cp.async chunk coords (4 x 16B for A, 4 x 16B for B per thread)
    // A tile: 128 rows x 32 cols; chunk e: row e>>3, 16B-chunk (e&7)
    // B tile: 32 k-rows x 128 cols; chunk e: k e>>5, 16B-chunk (e&31)
    const uint32_t a_smem_base = smem_u32(Asm);
    const uint32_t b_smem_base = smem_u32(Bsm);

    uint64_t acc[TM][TN / 2];
#pragma unroll
    for (int m = 0; m < TM; m++)
#pragma unroll
        for (int n = 0; n < TN / 2; n++) acc[m][n] = 0ull;

    // ---- issue tile loads for tile t into buffer buf
    auto issue_tile = [&](int t, int buf) {
        const int kt = t * BKT;
#pragma unroll
        for (int l = 0; l < 4; l++) {
            int e = tid + l * 256;
            int r = e >> 3;
            int c = (e & 7) * 4;
            cp_async16(a_smem_base +
                       (uint32_t)((buf * A_TILE_FLOATS + r * ASTRIDE + c) * 4),
                       &X[(size_t)(row0 + r) * ND + kt + c]);
        }
#pragma unroll
        for (int l = 0; l < 4; l++) {
            int e  = tid + l * 256;
            int kr = e >> 5;
            int c  = (e & 31) * 4;
            cp_async16(b_smem_base +
                       (uint32_t)((buf * B_TILE_FLOATS + kr * BN + c) * 4),
                       &g_W[(size_t)(kt + kr) * ND + col0 + c]);
        }
        cp_async_commit();
    };

    issue_tile(0, 0);
    cp_async_wait0();
    __syncthreads();

    for (int t = 0; t < NKT; t++) {
        const int buf = t & 1;

        if (t + 1 < NKT) issue_tile(t + 1, buf ^ 1);

        const float* At = Asm + buf * A_TILE_FLOATS + (ty * TM) * ASTRIDE;
        const float* Bt = Bsm + buf * B_TILE_FLOATS + tx * TN;

#pragma unroll
        for (int kk = 0; kk < BKT; kk++) {     // strict ascending k
            uint64_t a2[TM];
#pragma unroll
            for (int m = 0; m < TM; m++)
                a2[m] = dup_f32x2(At[m * ASTRIDE + kk]);   // scalar broadcast
            const float4 bv0 = *(const float4*)&Bt[kk * BN];
            const float4 bv1 = *(const float4*)&Bt[kk * BN + 4];
            uint64_t b2[TN / 2];
            b2[0] = ((const uint64_t*)&bv0)[0];
            b2[1] = ((const uint64_t*)&bv0)[1];
            b2[2] = ((const uint64_t*)&bv1)[0];
            b2[3] = ((const uint64_t*)&bv1)[1];
#pragma unroll
            for (int m = 0; m < TM; m++)
#pragma unroll
                for (int n = 0; n < TN / 2; n++)
                    ffma2(acc[m][n], a2[m], b2[n]);
        }

        if (t + 1 < NKT) {
            cp_async_wait0();
            __syncthreads();
        }
    }

    // ---- epilogue (identical math to R8/R12)
#pragma unroll
    for (int m = 0; m < TM; m++) {
        const int gi = row0 + ty * TM + m;
        const int gj0 = col0 + tx * TN;
        float out[TN];
#pragma unroll
        for (int n = 0; n < TN / 2; n++) {
            float lo, hi;
            unpack_f32x2(acc[m][n], lo, hi);
            uint32_t tl = ((uint32_t)gi << 10) | (uint32_t)(gj0 + 2 * n);
            out[2 * n]     = act(lo, rT, k0, k1, tl);
            out[2 * n + 1] = act(hi, rT, k0, k1, tl + 1);
        }
        float4* dst = (float4*)&O[(size_t)gi * ND + gj0];
        dst[0] = make_float4(out[0], out[1], out[2], out[3]);
        dst[1] = make_float4(out[4], out[5], out[6], out[7]);
    }
}

// ---------------------------------------------------------------- host side
static inline uint32_t h_rotl(uint32_t x, int r) { return (x << r) | (x >> (32 - r)); }
static void h_tf2x32(uint32_t k0, uint32_t k1, uint32_t c0, uint32_t c1,
                     uint32_t* o0, uint32_t* o1) {
    uint32_t ks2 = k0 ^ k1 ^ 0x1BD11BDAu;
    uint32_t x0 = c0 + k0, x1 = c1 + k1;
#define HTF_R(r) { x0 += x1; x1 = h_rotl(x1, (r)); x1 ^= x0; }
    HTF_R(13) HTF_R(15) HTF_R(26) HTF_R(6)   x0 += k1;  x1 += ks2 + 1u;
    HTF_R(17) HTF_R(29) HTF_R(16) HTF_R(24)  x0 += ks2; x1 += k0  + 2u;
    HTF_R(13) HTF_R(15) HTF_R(26) HTF_R(6)   x0 += k0;  x1 += k1  + 3u;
    HTF_R(17) HTF_R(29) HTF_R(16) HTF_R(24)  x0 += k1;  x1 += ks2 + 4u;
    HTF_R(13) HTF_R(15) HTF_R(26) HTF_R(6)   x0 += ks2; x1 += k0  + 5u;
#undef HTF_R
    *o0 = x0; *o1 = x1;
}

extern "C" void kernel_launch(void* const* d_in, const int* in_sizes, int n_in,
                              void* d_out, int out_size) {
    const float* x0 = (const float*)d_in[0];   // (65536, 1024) f32
    const float* Wu = (const float*)d_in[1];   // (1024, 1024)  f32

    float *xA, *xB;
    cudaGetSymbolAddress((void**)&xA, g_xA);
    cudaGetSymbolAddress((void**)&xB, g_xB);

    // allow 68KB dynamic smem (idempotent attribute set; not an allocation)
    cudaFuncSetAttribute(hop_step,
                         cudaFuncAttributeMaxDynamicSharedMemorySize,
                         SMEM_BYTES);

    prep_W<<<(ND * ND) / 256, 256>>>(Wu);

    uint32_t keys[10][2];
    for (int i = 0; i < 10; i++)
        h_tf2x32(0u, 42u, 0u, (uint32_t)i, &keys[i][0], &keys[i][1]);

    dim3 grid(ND / BN, NB / BM);   // (8, 512)
    const float* src = x0;
    for (int i = 0; i < 10; i++) {
        volatile float T  = (float)(1.0 / (double)(2 * i + 1));
        volatile float rT = 1.0f / T;
        float* dst = (i == 9) ? (float*)d_out : (((i & 1) == 0) ? xA : xB);
        hop_step<<<grid, 256, SMEM_BYTES>>>(src, dst, keys[i][0], keys[i][1], rT);
        src = dst;
    }
}